// round 14
// baseline (speedup 1.0000x reference)
#include <cuda_runtime.h>
#include <cuda_fp16.h>
#include <math.h>
#include <stdint.h>

#define BB 2
#define LL 512
#define HH 128
#define CC 49
#define NEGV 1000000000000.0f
#define NSM 148
#define NQUADS 1024           // 4096 tiles in quads of 4 consecutive i, same bjt
#define NBLK 7                // c padded to 56
#define NGRP 2                // 8-warp tile groups per CTA (512 threads)

// ---------------- device scratch (all f16, PERMUTED rows) ----------------
// permuted word layout per 128-h row (64 f16x2 words):
//   dest word 8k+2q+s  <-  orig word 8k+q+4s   (k=0..7, q=0..3, s=0..1)
__device__ __half  g_piP[BB * LL * HH];   // proj_i (Wh_b folded)
__device__ __half  g_pjh[BB * LL * HH];   // proj_j
__device__ __half  g_Rh[255 * HH];        // rel proj

__device__ __forceinline__ int permh(int h) {
    int m = h >> 1;
    int dw = (m & ~7) | ((m & 3) << 1) | ((m >> 2) & 1);
    return (dw << 1) | (h & 1);
}
__device__ __forceinline__ uint32_t pack_f16x2(float lo, float hi) {
    __half2 p = __floats2half2_rn(lo, hi);
    return *(uint32_t*)&p;
}
__device__ __forceinline__ uint32_t hadd2(uint32_t a, uint32_t b) {
    uint32_t d; asm("add.rn.f16x2 %0, %1, %2;" : "=r"(d) : "r"(a), "r"(b)); return d;
}
__device__ __forceinline__ uint32_t tanh2(uint32_t a) {
    uint32_t d; asm("tanh.approx.f16x2 %0, %1;" : "=r"(d) : "r"(a)); return d;
}
__device__ __forceinline__ void mma_f16acc(uint32_t* c, uint32_t a0, uint32_t a1,
                                           uint32_t a2, uint32_t a3,
                                           uint32_t b0, uint32_t b1) {
    asm volatile(
        "mma.sync.aligned.m16n8k16.row.col.f16.f16.f16.f16 "
        "{%0,%1}, {%2,%3,%4,%5}, {%6,%7}, {%0,%1};"
        : "+r"(c[0]), "+r"(c[1])
        : "r"(a0), "r"(a1), "r"(a2), "r"(a3), "r"(b0), "r"(b1));
}

// ---------------- prep kernel (R12/R13 verbatim) ----------------
#define PREP_SMEM (256 * 129 * 4 + 1056 * 4)
#define NUNITS_PREP 576

__global__ __launch_bounds__(512, 1)
void prep_kernel(const float* __restrict__ inputs,
                 const float* __restrict__ Wh_w,
                 const float* __restrict__ Wh_b,
                 const float* __restrict__ rel_pos)
{
    extern __shared__ float sm[];
    float* Wsm = sm;
    float* xs  = sm + 256 * 129;
    const int tid = threadIdx.x;

    for (int idx = tid; idx < 128 * 256; idx += 512) {
        int h = idx >> 8;
        int k = idx & 255;
        Wsm[k * 129 + h] = Wh_w[idx];
    }
    __syncthreads();

    for (int u = blockIdx.x; u < NUNITS_PREP; u += gridDim.x) {
        if (u < 512) {
            const int r0 = u * 2;
            if (tid < 256) {
                int row = tid >> 7, k = tid & 127;
                int l = (r0 + row) & (LL - 1);
                int i2 = k >> 1;
                float freq = exp2f(-(float)(2 * i2) * (13.287712379549449f / 128.0f));
                float ang = (float)l * freq;
                float em = (k & 1) ? cosf(ang) : sinf(ang);
                xs[row * 132 + k] = inputs[(r0 + row) * 128 + k] + em;
            }
            __syncthreads();
            {
                int row  = tid >> 8;
                int half = (tid >> 7) & 1;
                int h    = tid & 127;
                float s = half ? 0.0f : Wh_b[h];
                const float* wb = Wsm + half * 128 * 129 + h;
                const float* xr = xs + row * 132;
                #pragma unroll 8
                for (int kk = 0; kk < 128; kk++) s += xr[kk] * wb[kk * 129];
                const int r = r0 + row;
                if (half) g_pjh[r * 128 + permh(h)] = __float2half(s);
                else      g_piP[r * 128 + permh(h)] = __float2half(s);
            }
            __syncthreads();
        } else {
            const int g = u - 512;
            for (int idx = tid; idx < 1024; idx += 512) {
                int row = idx >> 8, k = idx & 255;
                int d = g * 4 + row;
                xs[row * 264 + k] = (d < 255)
                    ? rel_pos[(size_t)(127 * 512 + d) * 256 + k] : 0.0f;
            }
            __syncthreads();
            {
                int row = tid >> 7;
                int h   = tid & 127;
                int d = g * 4 + row;
                float s = 0.0f;
                const float* xr = xs + row * 264;
                const float* wb = Wsm + h;
                #pragma unroll 8
                for (int k = 0; k < 256; k++) s += xr[k] * wb[k * 129];
                if (d < 255) g_Rh[d * 128 + permh(h)] = __float2half(s);
            }
            __syncthreads();
        }
    }
}

// ---------------- main kernel smem layout (bytes) ----------------
#define ROWB 288
#define OFF_WOB  0                          // 64 f32
#define OFF_MASK 256                        // 1024 f32 -> 4352
#define OFF_B    4352                       // 28 slots * 512 = 14336 -> 18688
#define OFF_R    18688                      // 255*288 = 73440 -> 92128
#define OFF_PJ   92160                      // 2 groups * 128*288 = 73728 -> 165888
#define OFF_PI   165888                     // 2 groups * 2 bufs * 1024 = 4096 -> 169984
#define SMEM_MAIN 169984

__global__ __launch_bounds__(512, 1)
void main_kernel(const float* __restrict__ mask,
                 const float* __restrict__ Wo_w,
                 const float* __restrict__ Wo_b,
                 float* __restrict__ out)
{
    extern __shared__ char smc[];
    const int tid  = threadIdx.x;
    const int w    = tid >> 5;
    const int lane = tid & 31;
    const int gid  = lane >> 2;
    const int q2   = (lane & 3) << 1;
    const int grp  = w >> 3;           // 0..1
    const int wg   = w & 7;
    const int jl   = (wg << 4) + gid;
    const int jh   = jl + 8;

    // ---- stage wob + mask + R + B (CTA-wide, once) ----
    if (tid < 64) ((float*)(smc + OFF_WOB))[tid] = (tid < CC) ? Wo_b[tid] : 0.0f;
    for (int idx = tid; idx < BB * LL; idx += 512)
        ((float*)(smc + OFF_MASK))[idx] = mask[idx];
    for (int idx = tid; idx < 255 * 16; idx += 512) {
        const int row = idx >> 4;
        const int t   = idx & 15;
        *(uint4*)(smc + OFF_R + row * ROWB + t * 16) = ((const uint4*)g_Rh)[idx];
    }
    for (int s = w; s < 28; s += 16) {
        const int kp = s / 7;
        const int n  = s % 7;
        const int c  = n * 8 + gid;
        uint32_t b00 = 0, b01 = 0, b10 = 0, b11 = 0;
        if (c < CC) {
            const float* wp = Wo_w + c * 128 + kp * 32 + q2;
            b00 = pack_f16x2(wp[0],  wp[1]);
            b01 = pack_f16x2(wp[8],  wp[9]);
            b10 = pack_f16x2(wp[16], wp[17]);
            b11 = pack_f16x2(wp[24], wp[25]);
        }
        *(uint4*)(smc + OFF_B + (s * 32 + lane) * 16) = make_uint4(b00, b01, b10, b11);
    }
    __syncthreads();

    const float* maskS = (const float*)(smc + OFF_MASK);
    const float* wobp  = (const float*)(smc + OFF_WOB);

    // ---- group-local quad range ----
    const int gg = blockIdx.x * NGRP + grp;
    const int ng = gridDim.x * NGRP;
    const int q0 = (int)(((long long)gg * NQUADS) / ng);
    const int q1 = (int)(((long long)(gg + 1) * NQUADS) / ng);

    char* pjSlab = smc + OFF_PJ + grp * (128 * ROWB);
    char* piBufs = smc + OFF_PI + grp * 2048;
    // pj row rotation: 32B * ((row>>2)&1) -> uniform 2-per-bank-pair (2-wf LDS.64)
    const uint32_t pjlo_off = (uint32_t)(jl * ROWB) + 32u * ((jl >> 2) & 1) + q2 * 4;
    const uint32_t pjhi_off = (uint32_t)(jh * ROWB) + 32u * ((jh >> 2) & 1) + q2 * 4;

    uint32_t acc[4][NBLK][2];
    #pragma unroll
    for (int t = 0; t < 4; t++)
        #pragma unroll
        for (int n = 0; n < NBLK; n++) { acc[t][n][0] = 0u; acc[t][n][1] = 0u; }

    int prev_bjt = -1;
    int b = 0, j0 = 0, jg_lo = 0, jg_hi = 0;
    float mclo = 0.f, mchi = 0.f;

    for (int q = q0; q < q1; q++) {
        const int bjt = q >> 7;
        const int i0  = (q & 127) << 2;
        const int b_  = bjt >> 2;

        // stage pi quad (4 rows = 64 uint4), double-buffered by q parity
        if (wg == 0) {
            const uint4* src = (const uint4*)((const char*)g_piP +
                               ((size_t)((b_ << 9) + i0) << 8));
            uint4* dst = (uint4*)(piBufs + (q & 1) * 1024);
            dst[lane]      = src[lane];
            dst[lane + 32] = src[lane + 32];
        }
        if (bjt != prev_bjt) {
            asm volatile("bar.sync %0, 256;" :: "r"(grp + 1) : "memory"); // old-pj readers done
            prev_bjt = bjt;
            b  = b_;
            j0 = (bjt & 3) << 7;
            jg_lo = j0 + jl;
            jg_hi = j0 + jh;
            mclo = maskS[(b << 9) + jg_lo];
            mchi = maskS[(b << 9) + jg_hi];
            const uint4* src = (const uint4*)(g_pjh + ((b << 9) + j0) * 128);
            for (int idx = (wg << 5) + lane; idx < 2048; idx += 256) {
                const int row = idx >> 4;
                const uint32_t rot = 32u * ((row >> 2) & 1);
                *(uint4*)(pjSlab + row * ROWB + rot + (idx & 15) * 16) = src[idx];
            }
        }
        asm volatile("bar.sync %0, 256;" :: "r"(grp + 1) : "memory");

        uint32_t rl_off[4], rh_off[4];
        #pragma unroll
        for (int t = 0; t < 4; t++) {
            const int i = i0 + t;
            int dlo = jg_lo - i; dlo = dlo < -127 ? -127 : (dlo > 127 ? 127 : dlo);
            int dhi = jg_hi - i; dhi = dhi < -127 ? -127 : (dhi > 127 ? 127 : dhi);
            rl_off[t] = (uint32_t)((dlo + 127) * ROWB) + q2 * 4;
            rh_off[t] = (uint32_t)((dhi + 127) * ROWB) + q2 * 4;
        }
        const char* piB = piBufs + (q & 1) * 1024 + q2 * 4;

        #pragma unroll
        for (int kp = 0; kp < 4; kp++) {
            // pj fragments (t-invariant)
            const uint2 pl0 = *(const uint2*)(pjSlab + pjlo_off + kp * 64);
            const uint2 pl1 = *(const uint2*)(pjSlab + pjlo_off + kp * 64 + 32);
            const uint2 ph0 = *(const uint2*)(pjSlab + pjhi_off + kp * 64);
            const uint2 ph1 = *(const uint2*)(pjSlab + pjhi_off + kp * 64 + 32);

            // A fragments for all 4 tiles
            uint32_t A[4][8];
            #pragma unroll
            for (int t = 0; t < 4; t++) {
                const uint2 pi0 = *(const uint2*)(piB + t * 256 + kp * 64);
                const uint2 pi1 = *(const uint2*)(piB + t * 256 + kp * 64 + 32);
                const uint2 rl0 = *(const uint2*)(smc + OFF_R + rl_off[t] + kp * 64);
                const uint2 rl1 = *(const uint2*)(smc + OFF_R + rl_off[t] + kp * 64 + 32);
                const uint2 rh0 = *(const uint2*)(smc + OFF_R + rh_off[t] + kp * 64);
                const uint2 rh1 = *(const uint2*)(smc + OFF_R + rh_off[t] + kp * 64 + 32);
                A[t][0] = tanh2(hadd2(hadd2(pl0.x, rl0.x), pi0.x));
                A[t][1] = tanh2(hadd2(hadd2(ph0.x, rh0.x), pi0.x));
                A[t][2] = tanh2(hadd2(hadd2(pl0.y, rl0.y), pi0.y));
                A[t][3] = tanh2(hadd2(hadd2(ph0.y, rh0.y), pi0.y));
                A[t][4] = tanh2(hadd2(hadd2(pl1.x, rl1.x), pi1.x));
                A[t][5] = tanh2(hadd2(hadd2(ph1.x, rh1.x), pi1.x));
                A[t][6] = tanh2(hadd2(hadd2(pl1.y, rl1.y), pi1.y));
                A[t][7] = tanh2(hadd2(hadd2(ph1.y, rh1.y), pi1.y));
            }
            // B loaded once per (kp, n), shared across 4 tiles
            #pragma unroll
            for (int n = 0; n < NBLK; n++) {
                const uint4 bb = *(const uint4*)(smc + OFF_B + ((kp * 7 + n) * 32 + lane) * 16);
                #pragma unroll
                for (int t = 0; t < 4; t++) {
                    mma_f16acc(acc[t][n], A[t][0], A[t][1], A[t][2], A[t][3], bb.x, bb.y);
                    mma_f16acc(acc[t][n], A[t][4], A[t][5], A[t][6], A[t][7], bb.z, bb.w);
                }
            }
        }

        // ---- epilogue: bias, masks, tril, store ----
        const float adclo = NEGV * mclo - NEGV;
        const float adchi = NEGV * mchi - NEGV;
        #pragma unroll
        for (int t = 0; t < 4; t++) {
            const int i = i0 + t;
            const float mr = maskS[(b << 9) + i];
            const float addr_ = NEGV * mr - NEGV;
            const float trilo = (jg_lo < i) ? NEGV : 0.0f;
            const float trihi = (jg_hi < i) ? NEGV : 0.0f;
            float* ob = out + (size_t)b * CC * LL * LL + (size_t)i * LL;
            #pragma unroll
            for (int n = 0; n < NBLK; n++) {
                const int c0 = n * 8 + q2;
                const float2 wv = *(const float2*)(wobp + c0);
                const float2 lo = __half22float2(*(__half2*)&acc[t][n][0]);
                const float2 hi = __half22float2(*(__half2*)&acc[t][n][1]);
                float v0 = (lo.x + wv.x) * mr + addr_;
                float v1 = (lo.y + wv.y) * mr + addr_;
                float v2 = (hi.x + wv.x) * mr + addr_;
                float v3 = (hi.y + wv.y) * mr + addr_;
                v0 = v0 * mclo + adclo - trilo;
                v1 = v1 * mclo + adclo - trilo;
                v2 = v2 * mchi + adchi - trihi;
                v3 = v3 * mchi + adchi - trihi;
                if (c0 < CC) {
                    ob[(size_t)c0 * (LL * LL) + jg_lo] = v0;
                    ob[(size_t)c0 * (LL * LL) + jg_hi] = v2;
                }
                if (c0 + 1 < CC) {
                    ob[(size_t)(c0 + 1) * (LL * LL) + jg_lo] = v1;
                    ob[(size_t)(c0 + 1) * (LL * LL) + jg_hi] = v3;
                }
                acc[t][n][0] = 0u; acc[t][n][1] = 0u;
            }
        }
    }
}

// ---------------- launch ----------------
extern "C" void kernel_launch(void* const* d_in, const int* in_sizes, int n_in,
                              void* d_out, int out_size)
{
    const float* inputs = (const float*)d_in[0];
    const float* mask   = (const float*)d_in[1];
    const float* Wh_w   = (const float*)d_in[2];
    const float* Wh_b   = (const float*)d_in[3];
    const float* Wo_w   = (const float*)d_in[4];
    const float* Wo_b   = (const float*)d_in[5];
    const float* rel    = (const float*)d_in[6];
    float* out = (float*)d_out;

    cudaFuncSetAttribute(prep_kernel, cudaFuncAttributeMaxDynamicSharedMemorySize, PREP_SMEM);
    cudaFuncSetAttribute(main_kernel, cudaFuncAttributeMaxDynamicSharedMemorySize, SMEM_MAIN);

    prep_kernel<<<NSM, 512, PREP_SMEM>>>(inputs, Wh_w, Wh_b, rel);
    main_kernel<<<NSM, 512, SMEM_MAIN>>>(mask, Wo_w, Wo_b, out);
}

// round 15
// speedup vs baseline: 1.0289x; 1.0289x over previous
#include <cuda_runtime.h>
#include <cuda_fp16.h>
#include <math.h>
#include <stdint.h>

#define BB 2
#define LL 512
#define HH 128
#define CC 49
#define NEGV 1000000000000.0f
#define NSM 148
#define NPAIRS 2048           // 4096 tiles in pairs (i, i+1), same bjt
#define NBLK 7                // c padded to 56
#define NGRP 3                // 8-warp tile groups per CTA

// ---------------- device scratch (all f16, PERMUTED rows) ----------------
// permuted word layout per 128-h row (64 f16x2 words):
//   dest word 8k+2q+s  <-  orig word 8k+q+4s   (k=0..7, q=0..3, s=0..1)
__device__ __half  g_piP[BB * LL * HH];   // proj_i (Wh_b folded)
__device__ __half  g_pjh[BB * LL * HH];   // proj_j
__device__ __half  g_Rh[255 * HH];        // rel proj

__device__ __forceinline__ int permh(int h) {
    int m = h >> 1;
    int dw = (m & ~7) | ((m & 3) << 1) | ((m >> 2) & 1);
    return (dw << 1) | (h & 1);
}
__device__ __forceinline__ uint32_t pack_f16x2(float lo, float hi) {
    __half2 p = __floats2half2_rn(lo, hi);
    return *(uint32_t*)&p;
}
__device__ __forceinline__ uint32_t hadd2(uint32_t a, uint32_t b) {
    uint32_t d; asm("add.rn.f16x2 %0, %1, %2;" : "=r"(d) : "r"(a), "r"(b)); return d;
}
__device__ __forceinline__ uint32_t tanh2(uint32_t a) {
    uint32_t d; asm("tanh.approx.f16x2 %0, %1;" : "=r"(d) : "r"(a)); return d;
}
__device__ __forceinline__ void mma_f16acc(uint32_t* c, uint32_t a0, uint32_t a1,
                                           uint32_t a2, uint32_t a3,
                                           uint32_t b0, uint32_t b1) {
    asm volatile(
        "mma.sync.aligned.m16n8k16.row.col.f16.f16.f16.f16 "
        "{%0,%1}, {%2,%3,%4,%5}, {%6,%7}, {%0,%1};"
        : "+r"(c[0]), "+r"(c[1])
        : "r"(a0), "r"(a1), "r"(a2), "r"(a3), "r"(b0), "r"(b1));
}

// ---------------- prep kernel (verbatim, known-good) ----------------
#define PREP_SMEM (256 * 129 * 4 + 1056 * 4)
#define NUNITS_PREP 576

__global__ __launch_bounds__(512, 1)
void prep_kernel(const float* __restrict__ inputs,
                 const float* __restrict__ Wh_w,
                 const float* __restrict__ Wh_b,
                 const float* __restrict__ rel_pos)
{
    extern __shared__ float sm[];
    float* Wsm = sm;
    float* xs  = sm + 256 * 129;
    const int tid = threadIdx.x;

    for (int idx = tid; idx < 128 * 256; idx += 512) {
        int h = idx >> 8;
        int k = idx & 255;
        Wsm[k * 129 + h] = Wh_w[idx];
    }
    __syncthreads();

    for (int u = blockIdx.x; u < NUNITS_PREP; u += gridDim.x) {
        if (u < 512) {
            const int r0 = u * 2;
            if (tid < 256) {
                int row = tid >> 7, k = tid & 127;
                int l = (r0 + row) & (LL - 1);
                int i2 = k >> 1;
                float freq = exp2f(-(float)(2 * i2) * (13.287712379549449f / 128.0f));
                float ang = (float)l * freq;
                float em = (k & 1) ? cosf(ang) : sinf(ang);
                xs[row * 132 + k] = inputs[(r0 + row) * 128 + k] + em;
            }
            __syncthreads();
            {
                int row  = tid >> 8;
                int half = (tid >> 7) & 1;
                int h    = tid & 127;
                float s = half ? 0.0f : Wh_b[h];
                const float* wb = Wsm + half * 128 * 129 + h;
                const float* xr = xs + row * 132;
                #pragma unroll 8
                for (int kk = 0; kk < 128; kk++) s += xr[kk] * wb[kk * 129];
                const int r = r0 + row;
                if (half) g_pjh[r * 128 + permh(h)] = __float2half(s);
                else      g_piP[r * 128 + permh(h)] = __float2half(s);
            }
            __syncthreads();
        } else {
            const int g = u - 512;
            for (int idx = tid; idx < 1024; idx += 512) {
                int row = idx >> 8, k = idx & 255;
                int d = g * 4 + row;
                xs[row * 264 + k] = (d < 255)
                    ? rel_pos[(size_t)(127 * 512 + d) * 256 + k] : 0.0f;
            }
            __syncthreads();
            {
                int row = tid >> 7;
                int h   = tid & 127;
                int d = g * 4 + row;
                float s = 0.0f;
                const float* xr = xs + row * 264;
                const float* wb = Wsm + h;
                #pragma unroll 8
                for (int k = 0; k < 256; k++) s += xr[k] * wb[k * 129];
                if (d < 255) g_Rh[d * 128 + permh(h)] = __float2half(s);
            }
            __syncthreads();
        }
    }
}

// ---------------- main kernel smem layout (bytes) ----------------
#define ROWB 288                 // 72 words pitch
#define OFF_WOB  0               // 64 f32
#define OFF_MASK 256             // 1024 f32 -> 4352
#define OFF_B    4352            // 28 slots * 512 = 14336 -> 18688
#define OFF_R    18688           // 255*288 = 73440 -> 92128
#define OFF_PJ   92160           // 3 groups * 128*288 = 110592 -> 202752
#define OFF_PI   202752          // 3 groups * 2 bufs * 512 = 3072 -> 205824
#define SMEM_MAIN 205824

__global__ __launch_bounds__(768, 1)
void main_kernel(const float* __restrict__ mask,
                 const float* __restrict__ Wo_w,
                 const float* __restrict__ Wo_b,
                 float* __restrict__ out)
{
    extern __shared__ char smc[];
    const int tid  = threadIdx.x;
    const int w    = tid >> 5;
    const int lane = tid & 31;
    const int gid  = lane >> 2;
    const int q2   = (lane & 3) << 1;
    const int grp  = w >> 3;           // 0..2
    const int wg   = w & 7;
    const int jl   = (wg << 4) + gid;
    const int jh   = jl + 8;

    // ---- stage wob + mask + R + B (CTA-wide, once) ----
    if (tid < 64) ((float*)(smc + OFF_WOB))[tid] = (tid < CC) ? Wo_b[tid] : 0.0f;
    for (int idx = tid; idx < BB * LL; idx += 768)
        ((float*)(smc + OFF_MASK))[idx] = mask[idx];
    for (int idx = tid; idx < 255 * 16; idx += 768) {
        const int row = idx >> 4;
        const int t   = idx & 15;
        *(uint4*)(smc + OFF_R + row * ROWB + t * 16) = ((const uint4*)g_Rh)[idx];
    }
    for (int s = w; s < 28; s += 24) {
        const int kp = s / 7;
        const int n  = s % 7;
        const int c  = n * 8 + gid;
        uint32_t b00 = 0, b01 = 0, b10 = 0, b11 = 0;
        if (c < CC) {
            const float* wp = Wo_w + c * 128 + kp * 32 + q2;
            b00 = pack_f16x2(wp[0],  wp[1]);
            b01 = pack_f16x2(wp[8],  wp[9]);
            b10 = pack_f16x2(wp[16], wp[17]);
            b11 = pack_f16x2(wp[24], wp[25]);
        }
        *(uint4*)(smc + OFF_B + (s * 32 + lane) * 16) = make_uint4(b00, b01, b10, b11);
    }
    __syncthreads();

    const float* maskS = (const float*)(smc + OFF_MASK);
    const float* wobp  = (const float*)(smc + OFF_WOB);

    // ---- group-local pair range ----
    const int gg = blockIdx.x * NGRP + grp;
    const int ng = gridDim.x * NGRP;
    const int p0 = (int)(((long long)gg * NPAIRS) / ng);
    const int p1 = (int)(((long long)(gg + 1) * NPAIRS) / ng);

    char* pjSlab = smc + OFF_PJ + grp * (128 * ROWB);
    char* piBufs = smc + OFF_PI + grp * 1024;
    // pj row rotation: 32B * ((row>>2)&1) -> uniform bank coverage for LDS.64
    const uint32_t pjlo_off = (uint32_t)(jl * ROWB) + 32u * ((jl >> 2) & 1) + q2 * 4;
    const uint32_t pjhi_off = (uint32_t)(jh * ROWB) + 32u * ((jh >> 2) & 1) + q2 * 4;

    uint32_t acc[2][NBLK][2];
    #pragma unroll
    for (int t = 0; t < 2; t++)
        #pragma unroll
        for (int n = 0; n < NBLK; n++) { acc[t][n][0] = 0u; acc[t][n][1] = 0u; }

    int prev_bjt = -1;
    int b = 0, j0 = 0, jg_lo = 0, jg_hi = 0;
    float mclo = 0.f, mchi = 0.f;

    for (int p = p0; p < p1; p++) {
        const int bjt = p >> 8;
        const int i0  = (p & 255) << 1;

        // stage pi pair (double-buffered) — warp 0 of group
        if (wg == 0) {
            const uint4* src = (const uint4*)((const char*)g_piP +
                               ((size_t)(((bjt >> 2) << 9) + i0) << 8));
            *(uint4*)((char*)piBufs + (p & 1) * 512 + lane * 16) = src[lane];
        }
        if (bjt != prev_bjt) {
            asm volatile("bar.sync %0, 256;" :: "r"(grp + 1) : "memory"); // old-pj readers done
            prev_bjt = bjt;
            b  = bjt >> 2;
            j0 = (bjt & 3) << 7;
            jg_lo = j0 + jl;
            jg_hi = j0 + jh;
            mclo = maskS[(b << 9) + jg_lo];
            mchi = maskS[(b << 9) + jg_hi];
            // stage pj slab with bank rotation (group-cooperative: 256 threads)
            const uint4* src = (const uint4*)(g_pjh + ((b << 9) + j0) * 128);
            for (int idx = (wg << 5) + lane; idx < 2048; idx += 256) {
                const int row = idx >> 4;
                const uint32_t rot = 32u * ((row >> 2) & 1);
                *(uint4*)(pjSlab + row * ROWB + rot + (idx & 15) * 16) = src[idx];
            }
        }
        asm volatile("bar.sync %0, 256;" :: "r"(grp + 1) : "memory");

        uint32_t rl_off[2], rh_off[2];
        #pragma unroll
        for (int t = 0; t < 2; t++) {
            const int i = i0 + t;
            int dlo = jg_lo - i; dlo = dlo < -127 ? -127 : (dlo > 127 ? 127 : dlo);
            int dhi = jg_hi - i; dhi = dhi < -127 ? -127 : (dhi > 127 ? 127 : dhi);
            rl_off[t] = (uint32_t)((dlo + 127) * ROWB) + q2 * 4;
            rh_off[t] = (uint32_t)((dhi + 127) * ROWB) + q2 * 4;
        }
        const char* piB = piBufs + (p & 1) * 512 + q2 * 4;

        #pragma unroll
        for (int kp = 0; kp < 4; kp++) {
            // pj fragments (t-invariant, bank-rotated slab)
            const uint2 pl0 = *(const uint2*)(pjSlab + pjlo_off + kp * 64);
            const uint2 pl1 = *(const uint2*)(pjSlab + pjlo_off + kp * 64 + 32);
            const uint2 ph0 = *(const uint2*)(pjSlab + pjhi_off + kp * 64);
            const uint2 ph1 = *(const uint2*)(pjSlab + pjhi_off + kp * 64 + 32);

            uint32_t A[2][8];
            #pragma unroll
            for (int t = 0; t < 2; t++) {
                const uint2 pi0 = *(const uint2*)(piB + t * 256 + kp * 64);
                const uint2 pi1 = *(const uint2*)(piB + t * 256 + kp * 64 + 32);
                const uint2 rl0 = *(const uint2*)(smc + OFF_R + rl_off[t] + kp * 64);
                const uint2 rl1 = *(const uint2*)(smc + OFF_R + rl_off[t] + kp * 64 + 32);
                const uint2 rh0 = *(const uint2*)(smc + OFF_R + rh_off[t] + kp * 64);
                const uint2 rh1 = *(const uint2*)(smc + OFF_R + rh_off[t] + kp * 64 + 32);
                A[t][0] = tanh2(hadd2(hadd2(pl0.x, rl0.x), pi0.x));
                A[t][1] = tanh2(hadd2(hadd2(ph0.x, rh0.x), pi0.x));
                A[t][2] = tanh2(hadd2(hadd2(pl0.y, rl0.y), pi0.y));
                A[t][3] = tanh2(hadd2(hadd2(ph0.y, rh0.y), pi0.y));
                A[t][4] = tanh2(hadd2(hadd2(pl1.x, rl1.x), pi1.x));
                A[t][5] = tanh2(hadd2(hadd2(ph1.x, rh1.x), pi1.x));
                A[t][6] = tanh2(hadd2(hadd2(pl1.y, rl1.y), pi1.y));
                A[t][7] = tanh2(hadd2(hadd2(ph1.y, rh1.y), pi1.y));
            }
            #pragma unroll
            for (int n = 0; n < NBLK; n++) {
                const uint4 bb = *(const uint4*)(smc + OFF_B + ((kp * 7 + n) * 32 + lane) * 16);
                #pragma unroll
                for (int t = 0; t < 2; t++) {
                    mma_f16acc(acc[t][n], A[t][0], A[t][1], A[t][2], A[t][3], bb.x, bb.y);
                    mma_f16acc(acc[t][n], A[t][4], A[t][5], A[t][6], A[t][7], bb.z, bb.w);
                }
            }
        }

        // ---- epilogue: bias, masks, tril, store ----
        const float adclo = NEGV * mclo - NEGV;
        const float adchi = NEGV * mchi - NEGV;
        #pragma unroll
        for (int t = 0; t < 2; t++) {
            const int i = i0 + t;
            const float mr = maskS[(b << 9) + i];
            const float addr_ = NEGV * mr - NEGV;
            const float trilo = (jg_lo < i) ? NEGV : 0.0f;
            const float trihi = (jg_hi < i) ? NEGV : 0.0f;
            float* ob = out + (size_t)b * CC * LL * LL + (size_t)i * LL;
            #pragma unroll
            for (int n = 0; n < NBLK; n++) {
                const int c0 = n * 8 + q2;
                const float2 wv = *(const float2*)(wobp + c0);
                const float2 lo = __half22float2(*(__half2*)&acc[t][n][0]);
                const float2 hi = __half22float2(*(__half2*)&acc[t][n][1]);
                float v0 = (lo.x + wv.x) * mr + addr_;
                float v1 = (lo.y + wv.y) * mr + addr_;
                float v2 = (hi.x + wv.x) * mr + addr_;
                float v3 = (hi.y + wv.y) * mr + addr_;
                v0 = v0 * mclo + adclo - trilo;
                v1 = v1 * mclo + adclo - trilo;
                v2 = v2 * mchi + adchi - trihi;
                v3 = v3 * mchi + adchi - trihi;
                if (c0 < CC) {
                    ob[(size_t)c0 * (LL * LL) + jg_lo] = v0;
                    ob[(size_t)c0 * (LL * LL) + jg_hi] = v2;
                }
                if (c0 + 1 < CC) {
                    ob[(size_t)(c0 + 1) * (LL * LL) + jg_lo] = v1;
                    ob[(size_t)(c0 + 1) * (LL * LL) + jg_hi] = v3;
                }
                acc[t][n][0] = 0u; acc[t][n][1] = 0u;
            }
        }
    }
}

// ---------------- launch ----------------
extern "C" void kernel_launch(void* const* d_in, const int* in_sizes, int n_in,
                              void* d_out, int out_size)
{
    const float* inputs = (const float*)d_in[0];
    const float* mask   = (const float*)d_in[1];
    const float* Wh_w   = (const float*)d_in[2];
    const float* Wh_b   = (const float*)d_in[3];
    const float* Wo_w   = (const float*)d_in[4];
    const float* Wo_b   = (const float*)d_in[5];
    const float* rel    = (const float*)d_in[6];
    float* out = (float*)d_out;

    cudaFuncSetAttribute(prep_kernel, cudaFuncAttributeMaxDynamicSharedMemorySize, PREP_SMEM);
    cudaFuncSetAttribute(main_kernel, cudaFuncAttributeMaxDynamicSharedMemorySize, SMEM_MAIN);

    prep_kernel<<<NSM, 512, PREP_SMEM>>>(inputs, Wh_w, Wh_b, rel);
    main_kernel<<<NSM, 768, SMEM_MAIN>>>(mask, Wo_w, Wo_b, out);
}

// round 16
// speedup vs baseline: 1.1251x; 1.0934x over previous
#include <cuda_runtime.h>
#include <cuda_fp16.h>
#include <math.h>
#include <stdint.h>

#define BB 2
#define LL 512
#define HH 128
#define CC 49
#define NEGV 1000000000000.0f
#define NSM 148
#define NQUADS 1024           // 4096 tiles in quads: tile u = 4q + 2*grp + t
#define NBLK 7                // c padded to 56

// ---------------- device scratch (all f16, PERMUTED rows) ----------------
// permuted word layout per 128-h row (64 f16x2 words):
//   dest word 8k+2q+s  <-  orig word 8k+q+4s   (k=0..7, q=0..3, s=0..1)
__device__ __half  g_piP[BB * LL * HH];   // proj_i (Wh_b folded)
__device__ __half  g_pjh[BB * LL * HH];   // proj_j
__device__ __half  g_Rh[255 * HH];        // rel proj

__device__ __forceinline__ int permh(int h) {
    int m = h >> 1;
    int dw = (m & ~7) | ((m & 3) << 1) | ((m >> 2) & 1);
    return (dw << 1) | (h & 1);
}
__device__ __forceinline__ uint32_t pack_f16x2(float lo, float hi) {
    __half2 p = __floats2half2_rn(lo, hi);
    return *(uint32_t*)&p;
}
__device__ __forceinline__ uint32_t hadd2(uint32_t a, uint32_t b) {
    uint32_t d; asm("add.rn.f16x2 %0, %1, %2;" : "=r"(d) : "r"(a), "r"(b)); return d;
}
__device__ __forceinline__ uint32_t tanh2(uint32_t a) {
    uint32_t d; asm("tanh.approx.f16x2 %0, %1;" : "=r"(d) : "r"(a)); return d;
}
__device__ __forceinline__ void mma_f16acc(uint32_t* c, uint32_t a0, uint32_t a1,
                                           uint32_t a2, uint32_t a3,
                                           uint32_t b0, uint32_t b1) {
    asm volatile(
        "mma.sync.aligned.m16n8k16.row.col.f16.f16.f16.f16 "
        "{%0,%1}, {%2,%3,%4,%5}, {%6,%7}, {%0,%1};"
        : "+r"(c[0]), "+r"(c[1])
        : "r"(a0), "r"(a1), "r"(a2), "r"(a3), "r"(b0), "r"(b1));
}

// ---------------- prep kernel v4: W reads shared across row-pairs ----------------
// input units: 256 (4 rows each);  rel units: 32 (8 rows each)
#define PREP_SMEM (256 * 129 * 4 + 8 * 264 * 4)
#define NUNITS_PREP 288

__global__ __launch_bounds__(512, 1)
void prep_kernel(const float* __restrict__ inputs,
                 const float* __restrict__ Wh_w,
                 const float* __restrict__ Wh_b,
                 const float* __restrict__ rel_pos)
{
    extern __shared__ float sm[];
    float* Wsm = sm;                  // [k_glob][h] stride 129
    float* xs  = sm + 256 * 129;      // up to 8*264 floats
    const int tid = threadIdx.x;

    for (int idx = tid; idx < 128 * 256; idx += 512) {
        int h = idx >> 8;
        int k = idx & 255;
        Wsm[k * 129 + h] = Wh_w[idx];
    }
    __syncthreads();

    for (int u = blockIdx.x; u < NUNITS_PREP; u += gridDim.x) {
        if (u < 256) {
            // ---- 4 input rows r0..r0+3; threads pair rows to share W reads ----
            const int r0 = u * 4;
            {
                const int row = tid >> 7, k = tid & 127;
                const int l = (r0 + row) & (LL - 1);
                const int i2 = k >> 1;
                float freq = exp2f(-(float)(2 * i2) * (13.287712379549449f / 128.0f));
                float ang = (float)l * freq;
                float em = (k & 1) ? cosf(ang) : sinf(ang);
                xs[row * 132 + k] = inputs[(r0 + row) * 128 + k] + em;
            }
            __syncthreads();
            {
                const int h    = tid & 127;
                const int half = (tid >> 7) & 1;
                const int rp   = (tid >> 8) & 1;      // rows r0+2rp, r0+2rp+1
                float sa = half ? 0.0f : Wh_b[h];
                float sb = sa;
                const float* wb = Wsm + half * 128 * 129 + h;
                const float* xa = xs + (2 * rp) * 132;
                const float* xb = xs + (2 * rp + 1) * 132;
                #pragma unroll 8
                for (int kk = 0; kk < 128; kk++) {
                    const float wv = wb[kk * 129];
                    sa += xa[kk] * wv;
                    sb += xb[kk] * wv;
                }
                const int ra = r0 + 2 * rp;
                const int ph = permh(h);
                if (half) {
                    g_pjh[ra * 128 + ph]       = __float2half(sa);
                    g_pjh[(ra + 1) * 128 + ph] = __float2half(sb);
                } else {
                    g_piP[ra * 128 + ph]       = __float2half(sa);
                    g_piP[(ra + 1) * 128 + ph] = __float2half(sb);
                }
            }
            __syncthreads();
        } else {
            // ---- 8 rel rows d0..d0+7; threads pair rows to share W reads ----
            const int g = u - 256;
            const int d0 = g * 8;
            for (int idx = tid; idx < 2048; idx += 512) {
                const int row = idx >> 8, k = idx & 255;
                const int d = d0 + row;
                xs[row * 264 + k] = (d < 255)
                    ? rel_pos[(size_t)(127 * 512 + d) * 256 + k] : 0.0f;
            }
            __syncthreads();
            {
                const int h  = tid & 127;
                const int rp = tid >> 7;              // 0..3 -> rows d0+2rp, d0+2rp+1
                float sa = 0.0f, sb = 0.0f;
                const float* wb = Wsm + h;
                const float* xa = xs + (2 * rp) * 264;
                const float* xb = xs + (2 * rp + 1) * 264;
                #pragma unroll 8
                for (int k = 0; k < 256; k++) {
                    const float wv = wb[k * 129];
                    sa += xa[k] * wv;
                    sb += xb[k] * wv;
                }
                const int da = d0 + 2 * rp;
                const int ph = permh(h);
                if (da < 255)     g_Rh[da * 128 + ph]       = __float2half(sa);
                if (da + 1 < 255) g_Rh[(da + 1) * 128 + ph] = __float2half(sb);
            }
            __syncthreads();
        }
    }
}

// ---------------- main kernel (R12 verbatim, dead code removed) ----------------
#define ROWB 288                 // 72-word pitch: CF LDS.64 (verified R13/R15)
#define OFF_WOB  0               // 64 f32
#define OFF_MASK 256             // 1024 f32
#define OFF_B    4352            // 28 slots * 512
#define OFF_R    18688           // 255*288 = 73440
#define OFF_PI   92144           // 32 rows * 256B = 8192 (pi segment stage)
#define SMEM_MAIN (OFF_PI + 8192)

__global__ __launch_bounds__(512, 1)
void main_kernel(const float* __restrict__ mask,
                 const float* __restrict__ Wo_w,
                 const float* __restrict__ Wo_b,
                 float* __restrict__ out)
{
    extern __shared__ char smc[];
    const int tid  = threadIdx.x;
    const int w    = tid >> 5;
    const int lane = tid & 31;
    const int gid  = lane >> 2;
    const int q2   = (lane & 3) << 1;
    const int grp  = w >> 3;
    const int wg   = w & 7;
    const int jl   = (wg << 4) + gid;
    const int jh   = jl + 8;

    // ---- stage wob + mask + R + B ----
    if (tid < 64) ((float*)(smc + OFF_WOB))[tid] = (tid < CC) ? Wo_b[tid] : 0.0f;
    for (int idx = tid; idx < BB * LL; idx += 512)
        ((float*)(smc + OFF_MASK))[idx] = mask[idx];
    for (int idx = tid; idx < 255 * 16; idx += 512) {
        const int row = idx >> 4;
        const int t   = idx & 15;
        *(uint4*)(smc + OFF_R + row * ROWB + t * 16) = ((const uint4*)g_Rh)[idx];
    }
    for (int s = w; s < 28; s += 16) {
        const int kp = s / 7;
        const int n  = s % 7;
        const int c  = n * 8 + gid;
        uint32_t b00 = 0, b01 = 0, b10 = 0, b11 = 0;
        if (c < CC) {
            const float* wp = Wo_w + c * 128 + kp * 32 + q2;
            b00 = pack_f16x2(wp[0],  wp[1]);
            b01 = pack_f16x2(wp[8],  wp[9]);
            b10 = pack_f16x2(wp[16], wp[17]);
            b11 = pack_f16x2(wp[24], wp[25]);
        }
        *(uint4*)(smc + OFF_B + (s * 32 + lane) * 16) = make_uint4(b00, b01, b10, b11);
    }
    __syncthreads();

    const float* maskS = (const float*)(smc + OFF_MASK);
    const float* wobp  = (const float*)(smc + OFF_WOB);

    const int q0 = (int)(((long long)blockIdx.x * NQUADS) / gridDim.x);
    const int q1 = (int)(((long long)(blockIdx.x + 1) * NQUADS) / gridDim.x);

    uint32_t acc[2][NBLK][2];
    #pragma unroll
    for (int t = 0; t < 2; t++)
        #pragma unroll
        for (int n = 0; n < NBLK; n++) { acc[t][n][0] = 0u; acc[t][n][1] = 0u; }

    int q = q0;
    while (q < q1) {
        // ---------------- segment header (one bjt block) ----------------
        const int bjt = q >> 7;
        const int qe  = ((bjt + 1) << 7) < q1 ? ((bjt + 1) << 7) : q1;
        const int b   = bjt >> 2;
        const int j0  = (bjt & 3) << 7;
        const int jg_lo = j0 + jl;
        const int jg_hi = j0 + jh;

        // pj fragment share -> registers
        uint2 pjl0[4], pjl1[4], pjh0[4], pjh1[4];
        {
            const char* rlo = (const char*)g_pjh + (size_t)((b << 9) + jg_lo) * 256 + q2 * 4;
            const char* rhi = (const char*)g_pjh + (size_t)((b << 9) + jg_hi) * 256 + q2 * 4;
            #pragma unroll
            for (int kp = 0; kp < 4; kp++) {
                pjl0[kp] = *(const uint2*)(rlo + kp * 64);
                pjl1[kp] = *(const uint2*)(rlo + kp * 64 + 32);
                pjh0[kp] = *(const uint2*)(rhi + kp * 64);
                pjh1[kp] = *(const uint2*)(rhi + kp * 64 + 32);
            }
        }
        const float mclo = maskS[(b << 9) + jg_lo];
        const float mchi = maskS[(b << 9) + jg_hi];
        const float adclo = NEGV * mclo - NEGV;
        const float adchi = NEGV * mchi - NEGV;

        // stage this segment's pi rows into smem (<=28 rows)
        const int i_lo  = (q & 127) << 2;
        const int nrows = (qe - q) << 2;
        __syncthreads();   // prior segment's PI readers done
        {
            const uint4* src = (const uint4*)((const char*)g_piP +
                               ((size_t)((b << 9) + i_lo) << 8));
            for (int idx = tid; idx < nrows * 16; idx += 512)
                ((uint4*)(smc + OFF_PI))[idx] = src[idx];
        }
        __syncthreads();

        // ---------------- quad loop within segment ----------------
        for (; q < qe; q++) {
            const int i0 = ((q & 127) << 2) + (grp << 1);

            uint32_t rl_off[2], rh_off[2];
            const char* pip[2];
            #pragma unroll
            for (int t = 0; t < 2; t++) {
                const int i = i0 + t;
                int dlo = jg_lo - i; dlo = dlo < -127 ? -127 : (dlo > 127 ? 127 : dlo);
                int dhi = jg_hi - i; dhi = dhi < -127 ? -127 : (dhi > 127 ? 127 : dhi);
                rl_off[t] = (uint32_t)((dlo + 127) * ROWB) + q2 * 4;
                rh_off[t] = (uint32_t)((dhi + 127) * ROWB) + q2 * 4;
                pip[t] = smc + OFF_PI + (i - i_lo) * 256 + q2 * 4;
            }

            #pragma unroll
            for (int kp = 0; kp < 4; kp++) {
                uint32_t A[2][8];
                #pragma unroll
                for (int t = 0; t < 2; t++) {
                    const uint2 pi0 = *(const uint2*)(pip[t] + kp * 64);
                    const uint2 pi1 = *(const uint2*)(pip[t] + kp * 64 + 32);
                    const uint2 rl0 = *(const uint2*)(smc + OFF_R + rl_off[t] + kp * 64);
                    const uint2 rl1 = *(const uint2*)(smc + OFF_R + rl_off[t] + kp * 64 + 32);
                    const uint2 rh0 = *(const uint2*)(smc + OFF_R + rh_off[t] + kp * 64);
                    const uint2 rh1 = *(const uint2*)(smc + OFF_R + rh_off[t] + kp * 64 + 32);
                    A[t][0] = tanh2(hadd2(hadd2(pjl0[kp].x, rl0.x), pi0.x));
                    A[t][1] = tanh2(hadd2(hadd2(pjh0[kp].x, rh0.x), pi0.x));
                    A[t][2] = tanh2(hadd2(hadd2(pjl0[kp].y, rl0.y), pi0.y));
                    A[t][3] = tanh2(hadd2(hadd2(pjh0[kp].y, rh0.y), pi0.y));
                    A[t][4] = tanh2(hadd2(hadd2(pjl1[kp].x, rl1.x), pi1.x));
                    A[t][5] = tanh2(hadd2(hadd2(pjh1[kp].x, rh1.x), pi1.x));
                    A[t][6] = tanh2(hadd2(hadd2(pjl1[kp].y, rl1.y), pi1.y));
                    A[t][7] = tanh2(hadd2(hadd2(pjh1[kp].y, rh1.y), pi1.y));
                }
                #pragma unroll
                for (int n = 0; n < NBLK; n++) {
                    const uint4 bb = *(const uint4*)(smc + OFF_B + ((kp * 7 + n) * 32 + lane) * 16);
                    #pragma unroll
                    for (int t = 0; t < 2; t++) {
                        mma_f16acc(acc[t][n], A[t][0], A[t][1], A[t][2], A[t][3], bb.x, bb.y);
                        mma_f16acc(acc[t][n], A[t][4], A[t][5], A[t][6], A[t][7], bb.z, bb.w);
                    }
                }
            }

            // ---- epilogue: bias, masks, tril, store ----
            #pragma unroll
            for (int t = 0; t < 2; t++) {
                const int i = i0 + t;
                const float mr = maskS[(b << 9) + i];
                const float addr_ = NEGV * mr - NEGV;
                const float trilo = (jg_lo < i) ? NEGV : 0.0f;
                const float trihi = (jg_hi < i) ? NEGV : 0.0f;
                float* ob = out + (size_t)b * CC * LL * LL + (size_t)i * LL;
                #pragma unroll
                for (int n = 0; n < NBLK; n++) {
                    const int c0 = n * 8 + q2;
                    const float2 wv = *(const float2*)(wobp + c0);
                    const float2 lo = __half22float2(*(__half2*)&acc[t][n][0]);
                    const float2 hi = __half22float2(*(__half2*)&acc[t][n][1]);
                    float v0 = (lo.x + wv.x) * mr + addr_;
                    float v1 = (lo.y + wv.y) * mr + addr_;
                    float v2 = (hi.x + wv.x) * mr + addr_;
                    float v3 = (hi.y + wv.y) * mr + addr_;
                    v0 = v0 * mclo + adclo - trilo;
                    v1 = v1 * mclo + adclo - trilo;
                    v2 = v2 * mchi + adchi - trihi;
                    v3 = v3 * mchi + adchi - trihi;
                    if (c0 < CC) {
                        ob[(size_t)c0 * (LL * LL) + jg_lo] = v0;
                        ob[(size_t)c0 * (LL * LL) + jg_hi] = v2;
                    }
                    if (c0 + 1 < CC) {
                        ob[(size_t)(c0 + 1) * (LL * LL) + jg_lo] = v1;
                        ob[(size_t)(c0 + 1) * (LL * LL) + jg_hi] = v3;
                    }
                    acc[t][n][0] = 0u; acc[t][n][1] = 0u;
                }
            }
        }
    }
}

// ---------------- launch ----------------
extern "C" void kernel_launch(void* const* d_in, const int* in_sizes, int n_in,
                              void* d_out, int out_size)
{
    const float* inputs = (const float*)d_in[0];
    const float* mask   = (const float*)d_in[1];
    const float* Wh_w   = (const float*)d_in[2];
    const float* Wh_b   = (const float*)d_in[3];
    const float* Wo_w   = (const float*)d_in[4];
    const float* Wo_b   = (const float*)d_in[5];
    const float* rel    = (const float*)d_in[6];
    float* out = (float*)d_out;

    cudaFuncSetAttribute(prep_kernel, cudaFuncAttributeMaxDynamicSharedMemorySize, PREP_SMEM);
    cudaFuncSetAttribute(main_kernel, cudaFuncAttributeMaxDynamicSharedMemorySize, SMEM_MAIN);

    prep_kernel<<<NSM, 512, PREP_SMEM>>>(inputs, Wh_w, Wh_b, rel);
    main_kernel<<<NSM, 512, SMEM_MAIN>>>(mask, Wo_w, Wo_b, out);
}

// round 17
// speedup vs baseline: 1.1262x; 1.0010x over previous
#include <cuda_runtime.h>
#include <cuda_fp16.h>
#include <math.h>
#include <stdint.h>

#define BB 2
#define LL 512
#define HH 128
#define CC 49
#define NEGV 1000000000000.0f
#define NSM 148
#define NQUADS 1024           // 4096 tiles in quads: tile u = 4q + 2*grp + t
#define NBLK 7                // c padded to 56

// ---------------- device scratch (all f16, PERMUTED rows) ----------------
// permuted word layout per 128-h row (64 f16x2 words):
//   dest word 8k+2q+s  <-  orig word 8k+q+4s   (k=0..7, q=0..3, s=0..1)
__device__ __half  g_piP[BB * LL * HH];   // proj_i (Wh_b folded)
__device__ __half  g_pjh[BB * LL * HH];   // proj_j
__device__ __half  g_Rh[255 * HH];        // rel proj

__device__ __forceinline__ int permh(int h) {
    int m = h >> 1;
    int dw = (m & ~7) | ((m & 3) << 1) | ((m >> 2) & 1);
    return (dw << 1) | (h & 1);
}
__device__ __forceinline__ uint32_t pack_f16x2(float lo, float hi) {
    __half2 p = __floats2half2_rn(lo, hi);
    return *(uint32_t*)&p;
}
__device__ __forceinline__ uint32_t hadd2(uint32_t a, uint32_t b) {
    uint32_t d; asm("add.rn.f16x2 %0, %1, %2;" : "=r"(d) : "r"(a), "r"(b)); return d;
}
__device__ __forceinline__ uint32_t tanh2(uint32_t a) {
    uint32_t d; asm("tanh.approx.f16x2 %0, %1;" : "=r"(d) : "r"(a)); return d;
}
__device__ __forceinline__ void mma_f16acc(uint32_t* c, uint32_t a0, uint32_t a1,
                                           uint32_t a2, uint32_t a3,
                                           uint32_t b0, uint32_t b1) {
    asm volatile(
        "mma.sync.aligned.m16n8k16.row.col.f16.f16.f16.f16 "
        "{%0,%1}, {%2,%3,%4,%5}, {%6,%7}, {%0,%1};"
        : "+r"(c[0]), "+r"(c[1])
        : "r"(a0), "r"(a1), "r"(a2), "r"(a3), "r"(b0), "r"(b1));
}

// ---------------- prep kernel v4: W reads shared across row-pairs ----------------
// input units: 256 (4 rows each);  rel units: 32 (8 rows each)
#define PREP_SMEM (256 * 129 * 4 + 8 * 264 * 4)
#define NUNITS_PREP 288

__global__ __launch_bounds__(512, 1)
void prep_kernel(const float* __restrict__ inputs,
                 const float* __restrict__ Wh_w,
                 const float* __restrict__ Wh_b,
                 const float* __restrict__ rel_pos)
{
    extern __shared__ float sm[];
    float* Wsm = sm;                  // [k_glob][h] stride 129
    float* xs  = sm + 256 * 129;      // up to 8*264 floats
    const int tid = threadIdx.x;

    for (int idx = tid; idx < 128 * 256; idx += 512) {
        int h = idx >> 8;
        int k = idx & 255;
        Wsm[k * 129 + h] = Wh_w[idx];
    }
    __syncthreads();

    for (int u = blockIdx.x; u < NUNITS_PREP; u += gridDim.x) {
        if (u < 256) {
            // ---- 4 input rows r0..r0+3; threads pair rows to share W reads ----
            const int r0 = u * 4;
            {
                const int row = tid >> 7, k = tid & 127;
                const int l = (r0 + row) & (LL - 1);
                const int i2 = k >> 1;
                float freq = exp2f(-(float)(2 * i2) * (13.287712379549449f / 128.0f));
                float ang = (float)l * freq;
                float em = (k & 1) ? cosf(ang) : sinf(ang);
                xs[row * 132 + k] = inputs[(r0 + row) * 128 + k] + em;
            }
            __syncthreads();
            {
                const int h    = tid & 127;
                const int half = (tid >> 7) & 1;
                const int rp   = (tid >> 8) & 1;      // rows r0+2rp, r0+2rp+1
                float sa = half ? 0.0f : Wh_b[h];
                float sb = sa;
                const float* wb = Wsm + half * 128 * 129 + h;
                const float* xa = xs + (2 * rp) * 132;
                const float* xb = xs + (2 * rp + 1) * 132;
                #pragma unroll 8
                for (int kk = 0; kk < 128; kk++) {
                    const float wv = wb[kk * 129];
                    sa += xa[kk] * wv;
                    sb += xb[kk] * wv;
                }
                const int ra = r0 + 2 * rp;
                const int ph = permh(h);
                if (half) {
                    g_pjh[ra * 128 + ph]       = __float2half(sa);
                    g_pjh[(ra + 1) * 128 + ph] = __float2half(sb);
                } else {
                    g_piP[ra * 128 + ph]       = __float2half(sa);
                    g_piP[(ra + 1) * 128 + ph] = __float2half(sb);
                }
            }
            __syncthreads();
        } else {
            // ---- 8 rel rows d0..d0+7; threads pair rows to share W reads ----
            const int g = u - 256;
            const int d0 = g * 8;
            for (int idx = tid; idx < 2048; idx += 512) {
                const int row = idx >> 8, k = idx & 255;
                const int d = d0 + row;
                xs[row * 264 + k] = (d < 255)
                    ? rel_pos[(size_t)(127 * 512 + d) * 256 + k] : 0.0f;
            }
            __syncthreads();
            {
                const int h  = tid & 127;
                const int rp = tid >> 7;              // 0..3 -> rows d0+2rp, d0+2rp+1
                float sa = 0.0f, sb = 0.0f;
                const float* wb = Wsm + h;
                const float* xa = xs + (2 * rp) * 264;
                const float* xb = xs + (2 * rp + 1) * 264;
                #pragma unroll 8
                for (int k = 0; k < 256; k++) {
                    const float wv = wb[k * 129];
                    sa += xa[k] * wv;
                    sb += xb[k] * wv;
                }
                const int da = d0 + 2 * rp;
                const int ph = permh(h);
                if (da < 255)     g_Rh[da * 128 + ph]       = __float2half(sa);
                if (da + 1 < 255) g_Rh[(da + 1) * 128 + ph] = __float2half(sb);
            }
            __syncthreads();
        }
    }
}

// ---------------- main kernel (R12 verbatim, dead code removed) ----------------
#define ROWB 288                 // 72-word pitch: CF LDS.64 (verified R13/R15)
#define OFF_WOB  0               // 64 f32
#define OFF_MASK 256             // 1024 f32
#define OFF_B    4352            // 28 slots * 512
#define OFF_R    18688           // 255*288 = 73440
#define OFF_PI   92144           // 32 rows * 256B = 8192 (pi segment stage)
#define SMEM_MAIN (OFF_PI + 8192)

__global__ __launch_bounds__(512, 1)
void main_kernel(const float* __restrict__ mask,
                 const float* __restrict__ Wo_w,
                 const float* __restrict__ Wo_b,
                 float* __restrict__ out)
{
    extern __shared__ char smc[];
    const int tid  = threadIdx.x;
    const int w    = tid >> 5;
    const int lane = tid & 31;
    const int gid  = lane >> 2;
    const int q2   = (lane & 3) << 1;
    const int grp  = w >> 3;
    const int wg   = w & 7;
    const int jl   = (wg << 4) + gid;
    const int jh   = jl + 8;

    // ---- stage wob + mask + R + B ----
    if (tid < 64) ((float*)(smc + OFF_WOB))[tid] = (tid < CC) ? Wo_b[tid] : 0.0f;
    for (int idx = tid; idx < BB * LL; idx += 512)
        ((float*)(smc + OFF_MASK))[idx] = mask[idx];
    for (int idx = tid; idx < 255 * 16; idx += 512) {
        const int row = idx >> 4;
        const int t   = idx & 15;
        *(uint4*)(smc + OFF_R + row * ROWB + t * 16) = ((const uint4*)g_Rh)[idx];
    }
    for (int s = w; s < 28; s += 16) {
        const int kp = s / 7;
        const int n  = s % 7;
        const int c  = n * 8 + gid;
        uint32_t b00 = 0, b01 = 0, b10 = 0, b11 = 0;
        if (c < CC) {
            const float* wp = Wo_w + c * 128 + kp * 32 + q2;
            b00 = pack_f16x2(wp[0],  wp[1]);
            b01 = pack_f16x2(wp[8],  wp[9]);
            b10 = pack_f16x2(wp[16], wp[17]);
            b11 = pack_f16x2(wp[24], wp[25]);
        }
        *(uint4*)(smc + OFF_B + (s * 32 + lane) * 16) = make_uint4(b00, b01, b10, b11);
    }
    __syncthreads();

    const float* maskS = (const float*)(smc + OFF_MASK);
    const float* wobp  = (const float*)(smc + OFF_WOB);

    const int q0 = (int)(((long long)blockIdx.x * NQUADS) / gridDim.x);
    const int q1 = (int)(((long long)(blockIdx.x + 1) * NQUADS) / gridDim.x);

    uint32_t acc[2][NBLK][2];
    #pragma unroll
    for (int t = 0; t < 2; t++)
        #pragma unroll
        for (int n = 0; n < NBLK; n++) { acc[t][n][0] = 0u; acc[t][n][1] = 0u; }

    int q = q0;
    while (q < q1) {
        // ---------------- segment header (one bjt block) ----------------
        const int bjt = q >> 7;
        const int qe  = ((bjt + 1) << 7) < q1 ? ((bjt + 1) << 7) : q1;
        const int b   = bjt >> 2;
        const int j0  = (bjt & 3) << 7;
        const int jg_lo = j0 + jl;
        const int jg_hi = j0 + jh;

        // pj fragment share -> registers
        uint2 pjl0[4], pjl1[4], pjh0[4], pjh1[4];
        {
            const char* rlo = (const char*)g_pjh + (size_t)((b << 9) + jg_lo) * 256 + q2 * 4;
            const char* rhi = (const char*)g_pjh + (size_t)((b << 9) + jg_hi) * 256 + q2 * 4;
            #pragma unroll
            for (int kp = 0; kp < 4; kp++) {
                pjl0[kp] = *(const uint2*)(rlo + kp * 64);
                pjl1[kp] = *(const uint2*)(rlo + kp * 64 + 32);
                pjh0[kp] = *(const uint2*)(rhi + kp * 64);
                pjh1[kp] = *(const uint2*)(rhi + kp * 64 + 32);
            }
        }
        const float mclo = maskS[(b << 9) + jg_lo];
        const float mchi = maskS[(b << 9) + jg_hi];
        const float adclo = NEGV * mclo - NEGV;
        const float adchi = NEGV * mchi - NEGV;

        // stage this segment's pi rows into smem (<=28 rows)
        const int i_lo  = (q & 127) << 2;
        const int nrows = (qe - q) << 2;
        __syncthreads();   // prior segment's PI readers done
        {
            const uint4* src = (const uint4*)((const char*)g_piP +
                               ((size_t)((b << 9) + i_lo) << 8));
            for (int idx = tid; idx < nrows * 16; idx += 512)
                ((uint4*)(smc + OFF_PI))[idx] = src[idx];
        }
        __syncthreads();

        // ---------------- quad loop within segment ----------------
        for (; q < qe; q++) {
            const int i0 = ((q & 127) << 2) + (grp << 1);

            uint32_t rl_off[2], rh_off[2];
            const char* pip[2];
            #pragma unroll
            for (int t = 0; t < 2; t++) {
                const int i = i0 + t;
                int dlo = jg_lo - i; dlo = dlo < -127 ? -127 : (dlo > 127 ? 127 : dlo);
                int dhi = jg_hi - i; dhi = dhi < -127 ? -127 : (dhi > 127 ? 127 : dhi);
                rl_off[t] = (uint32_t)((dlo + 127) * ROWB) + q2 * 4;
                rh_off[t] = (uint32_t)((dhi + 127) * ROWB) + q2 * 4;
                pip[t] = smc + OFF_PI + (i - i_lo) * 256 + q2 * 4;
            }

            #pragma unroll
            for (int kp = 0; kp < 4; kp++) {
                uint32_t A[2][8];
                #pragma unroll
                for (int t = 0; t < 2; t++) {
                    const uint2 pi0 = *(const uint2*)(pip[t] + kp * 64);
                    const uint2 pi1 = *(const uint2*)(pip[t] + kp * 64 + 32);
                    const uint2 rl0 = *(const uint2*)(smc + OFF_R + rl_off[t] + kp * 64);
                    const uint2 rl1 = *(const uint2*)(smc + OFF_R + rl_off[t] + kp * 64 + 32);
                    const uint2 rh0 = *(const uint2*)(smc + OFF_R + rh_off[t] + kp * 64);
                    const uint2 rh1 = *(const uint2*)(smc + OFF_R + rh_off[t] + kp * 64 + 32);
                    A[t][0] = tanh2(hadd2(hadd2(pjl0[kp].x, rl0.x), pi0.x));
                    A[t][1] = tanh2(hadd2(hadd2(pjh0[kp].x, rh0.x), pi0.x));
                    A[t][2] = tanh2(hadd2(hadd2(pjl0[kp].y, rl0.y), pi0.y));
                    A[t][3] = tanh2(hadd2(hadd2(pjh0[kp].y, rh0.y), pi0.y));
                    A[t][4] = tanh2(hadd2(hadd2(pjl1[kp].x, rl1.x), pi1.x));
                    A[t][5] = tanh2(hadd2(hadd2(pjh1[kp].x, rh1.x), pi1.x));
                    A[t][6] = tanh2(hadd2(hadd2(pjl1[kp].y, rl1.y), pi1.y));
                    A[t][7] = tanh2(hadd2(hadd2(pjh1[kp].y, rh1.y), pi1.y));
                }
                #pragma unroll
                for (int n = 0; n < NBLK; n++) {
                    const uint4 bb = *(const uint4*)(smc + OFF_B + ((kp * 7 + n) * 32 + lane) * 16);
                    #pragma unroll
                    for (int t = 0; t < 2; t++) {
                        mma_f16acc(acc[t][n], A[t][0], A[t][1], A[t][2], A[t][3], bb.x, bb.y);
                        mma_f16acc(acc[t][n], A[t][4], A[t][5], A[t][6], A[t][7], bb.z, bb.w);
                    }
                }
            }

            // ---- epilogue: bias, masks, tril, store ----
            #pragma unroll
            for (int t = 0; t < 2; t++) {
                const int i = i0 + t;
                const float mr = maskS[(b << 9) + i];
                const float addr_ = NEGV * mr - NEGV;
                const float trilo = (jg_lo < i) ? NEGV : 0.0f;
                const float trihi = (jg_hi < i) ? NEGV : 0.0f;
                float* ob = out + (size_t)b * CC * LL * LL + (size_t)i * LL;
                #pragma unroll
                for (int n = 0; n < NBLK; n++) {
                    const int c0 = n * 8 + q2;
                    const float2 wv = *(const float2*)(wobp + c0);
                    const float2 lo = __half22float2(*(__half2*)&acc[t][n][0]);
                    const float2 hi = __half22float2(*(__half2*)&acc[t][n][1]);
                    float v0 = (lo.x + wv.x) * mr + addr_;
                    float v1 = (lo.y + wv.y) * mr + addr_;
                    float v2 = (hi.x + wv.x) * mr + addr_;
                    float v3 = (hi.y + wv.y) * mr + addr_;
                    v0 = v0 * mclo + adclo - trilo;
                    v1 = v1 * mclo + adclo - trilo;
                    v2 = v2 * mchi + adchi - trihi;
                    v3 = v3 * mchi + adchi - trihi;
                    if (c0 < CC) {
                        ob[(size_t)c0 * (LL * LL) + jg_lo] = v0;
                        ob[(size_t)c0 * (LL * LL) + jg_hi] = v2;
                    }
                    if (c0 + 1 < CC) {
                        ob[(size_t)(c0 + 1) * (LL * LL) + jg_lo] = v1;
                        ob[(size_t)(c0 + 1) * (LL * LL) + jg_hi] = v3;
                    }
                    acc[t][n][0] = 0u; acc[t][n][1] = 0u;
                }
            }
        }
    }
}

// ---------------- launch ----------------
extern "C" void kernel_launch(void* const* d_in, const int* in_sizes, int n_in,
                              void* d_out, int out_size)
{
    const float* inputs = (const float*)d_in[0];
    const float* mask   = (const float*)d_in[1];
    const float* Wh_w   = (const float*)d_in[2];
    const float* Wh_b   = (const float*)d_in[3];
    const float* Wo_w   = (const float*)d_in[4];
    const float* Wo_b   = (const float*)d_in[5];
    const float* rel    = (const float*)d_in[6];
    float* out = (float*)d_out;

    cudaFuncSetAttribute(prep_kernel, cudaFuncAttributeMaxDynamicSharedMemorySize, PREP_SMEM);
    cudaFuncSetAttribute(main_kernel, cudaFuncAttributeMaxDynamicSharedMemorySize, SMEM_MAIN);

    prep_kernel<<<NSM, 512, PREP_SMEM>>>(inputs, Wh_w, Wh_b, rel);
    main_kernel<<<NSM, 512, SMEM_MAIN>>>(mask, Wo_w, Wo_b, out);
}